// round 1
// baseline (speedup 1.0000x reference)
#include <cuda_runtime.h>
#include <math.h>

#define NP 16384
#define NR 8192
#define GRIDN 13
#define NCELL (GRIDN*GRIDN*GRIDN)
#define CAP 64
#define RADIUS2 (0.075f*0.075f)

// ---------------- static scratch (no allocations allowed) ----------------
__device__ int    d_cellCnt[NCELL];
__device__ float4 d_cellPts[NCELL*CAP];
__device__ int    d_nbr[NP*3];
__device__ float  d_bufA[384*NP];   // 25.2 MB
__device__ float  d_bufB[384*NP];   // 25.2 MB
__device__ float  d_bufC[256*NP];   // 16.8 MB
__device__ float  d_bns[5*384];
__device__ float  d_bnt[5*384];

// ---------------- spatial grid build ----------------
__global__ void k_clear() {
    int i = blockIdx.x*blockDim.x + threadIdx.x;
    if (i < NCELL) d_cellCnt[i] = 0;
}

__device__ __forceinline__ int cidx(float v) {
    int c = (int)(v * (float)GRIDN);
    return c < 0 ? 0 : (c > GRIDN-1 ? GRIDN-1 : c);
}

__global__ void k_build(const float* __restrict__ rgb) {
    int i = blockIdx.x*blockDim.x + threadIdx.x;
    if (i >= NR) return;
    float x = rgb[3*i], y = rgb[3*i+1], z = rgb[3*i+2];
    int c = (cidx(x)*GRIDN + cidx(y))*GRIDN + cidx(z);
    int p = atomicAdd(&d_cellCnt[c], 1);
    if (p < CAP) d_cellPts[c*CAP + p] = make_float4(x, y, z, __int_as_float(i));
}

// ---------------- 3-NN within radius via 27-cell search ----------------
__global__ void k_3nn(const float* __restrict__ pcd) {
    int i = blockIdx.x*blockDim.x + threadIdx.x;
    if (i >= NP) return;
    float x = pcd[3*i], y = pcd[3*i+1], z = pcd[3*i+2];
    int cx = cidx(x), cy = cidx(y), cz = cidx(z);
    int x0 = max(cx-1,0), x1 = min(cx+1,GRIDN-1);
    int y0 = max(cy-1,0), y1 = min(cy+1,GRIDN-1);
    int z0 = max(cz-1,0), z1 = min(cz+1,GRIDN-1);
    float b0 = 3.4e38f, b1 = 3.4e38f, b2 = 3.4e38f;
    int   i0 = NR, i1 = NR, i2 = NR;
    for (int ax = x0; ax <= x1; ax++)
    for (int ay = y0; ay <= y1; ay++)
    for (int az = z0; az <= z1; az++) {
        int c = (ax*GRIDN + ay)*GRIDN + az;
        int cnt = min(d_cellCnt[c], CAP);
        const float4* pts = &d_cellPts[c*CAP];
        for (int p = 0; p < cnt; p++) {
            float4 q = pts[p];
            float dx = x - q.x, dy = y - q.y, dz = z - q.z;
            float d = fmaf(dx, dx, fmaf(dy, dy, dz*dz));
            if (d <= RADIUS2 && d < b2) {
                int qi = __float_as_int(q.w);
                if (d < b0)      { b2=b1;i2=i1; b1=b0;i1=i0; b0=d;i0=qi; }
                else if (d < b1) { b2=b1;i2=i1; b1=d; i1=qi; }
                else             { b2=d; i2=qi; }
            }
        }
    }
    d_nbr[3*i] = i0; d_nbr[3*i+1] = i1; d_nbr[3*i+2] = i2;
}

// ---------------- gather neighbor features -> x_cat (bufA rows 0..383)
// ---------------- and max_features -> bufC rows 128..255
__global__ void k_gather(const float* __restrict__ rgbf) {
    int t = blockIdx.x*blockDim.x + threadIdx.x;
    if (t >= NP*128) return;
    int n = t & (NP-1);
    int c = t >> 14;
    int n0 = d_nbr[3*n], n1 = d_nbr[3*n+1], n2 = d_nbr[3*n+2];
    const float* row = rgbf + (size_t)c * NR;
    float v0 = n0 < NR ? row[n0] : 0.f;
    float v1 = n1 < NR ? row[n1] : 0.f;
    float v2 = n2 < NR ? row[n2] : 0.f;
    d_bufA[(size_t)c*NP + n]       = v0;
    d_bufA[(size_t)(128+c)*NP + n] = v1;
    d_bufA[(size_t)(256+c)*NP + n] = v2;
    d_bufC[(size_t)(128+c)*NP + n] = fmaxf(fmaxf(v0, v1), v2);
}

// ---------------- fold eval-mode BN into scale/shift ----------------
__global__ void k_bnprep(const float* __restrict__ bn, int C, int slot) {
    int c = blockIdx.x*blockDim.x + threadIdx.x;
    if (c >= C) return;
    float g = bn[c], b = bn[C+c], m = bn[2*C+c], v = bn[3*C+c];
    float s = g * rsqrtf(v + 1e-5f);
    d_bns[slot*384 + c] = s;
    d_bnt[slot*384 + c] = b - m*s;
}

// ---------------- fp32 tiled GEMM: Y(M,NP) = W(M,K) @ X(K,NP) + bias,
// optionally fused BN+ReLU. BM=BN=64, BK=16, TM=TN=4, 256 threads.
template<bool BNRELU>
__global__ void k_gemm(const float* __restrict__ W, const float* __restrict__ X,
                       float* __restrict__ Y, const float* __restrict__ bias,
                       const float* __restrict__ bns, const float* __restrict__ bnt,
                       int M, int K) {
    const int BM = 64, BN = 64, BK = 16, TM = 4, TN = 4;
    __shared__ float As[BK][BM];
    __shared__ float Bs[BK][BN];
    int bm = blockIdx.y * BM, bn = blockIdx.x * BN;
    int tid = threadIdx.x;
    int tx = tid % 16, ty = tid / 16;
    float acc[TM][TN] = {};
    for (int k0 = 0; k0 < K; k0 += BK) {
        {   // A: As[k][m] = W[(bm+m)*K + k0+k]
            int k = tid & 15, mb = tid >> 4;
            #pragma unroll
            for (int r = 0; r < 4; r++) {
                int m = mb + r*16;
                As[k][m] = (bm + m < M) ? W[(size_t)(bm+m)*K + k0 + k] : 0.f;
            }
        }
        {   // B: Bs[k][n] = X[(k0+k)*NP + bn+n]  (coalesced)
            int n = tid & 63, kb = tid >> 6;
            #pragma unroll
            for (int r = 0; r < 4; r++) {
                int k = kb + r*4;
                Bs[k][n] = X[(size_t)(k0+k)*NP + bn + n];
            }
        }
        __syncthreads();
        #pragma unroll
        for (int kk = 0; kk < BK; kk++) {
            float a[TM], b[TN];
            #pragma unroll
            for (int i = 0; i < TM; i++) a[i] = As[kk][ty*TM + i];
            #pragma unroll
            for (int j = 0; j < TN; j++) b[j] = Bs[kk][tx*TN + j];
            #pragma unroll
            for (int i = 0; i < TM; i++)
                #pragma unroll
                for (int j = 0; j < TN; j++)
                    acc[i][j] = fmaf(a[i], b[j], acc[i][j]);
        }
        __syncthreads();
    }
    #pragma unroll
    for (int i = 0; i < TM; i++) {
        int m = bm + ty*TM + i;
        if (m >= M) continue;
        float bi = bias[m];
        float s = 0.f, t = 0.f;
        if (BNRELU) { s = bns[m]; t = bnt[m]; }
        #pragma unroll
        for (int j = 0; j < TN; j++) {
            float v = acc[i][j] + bi;
            if (BNRELU) v = fmaxf(fmaf(v, s, t), 0.f);
            Y[(size_t)m*NP + bn + tx*TN + j] = v;
        }
    }
}

// ---------------- score head: sigmoid(sh2_w . s + sh2_b), s in bufC ----------------
__global__ void k_score(const float* __restrict__ w, const float* __restrict__ b,
                        float* __restrict__ out) {
    int n = blockIdx.x*blockDim.x + threadIdx.x;
    if (n >= NP) return;
    float acc = b[0];
    #pragma unroll 8
    for (int c = 0; c < 128; c++)
        acc = fmaf(__ldg(&w[c]), d_bufC[(size_t)c*NP + n], acc);
    out[n] = 1.f / (1.f + expf(-acc));
}

// ---------------- L2-normalize fp (bufB, 128 x NP) -> out (NP x 128) ----------------
__global__ void k_vf(float* __restrict__ out) {
    int gtid = blockIdx.x*blockDim.x + threadIdx.x;
    int n = gtid >> 5;
    int lane = gtid & 31;
    if (n >= NP) return;
    float v[4]; float ss = 0.f;
    #pragma unroll
    for (int r = 0; r < 4; r++) {
        v[r] = d_bufB[(size_t)(lane + 32*r)*NP + n];
        ss = fmaf(v[r], v[r], ss);
    }
    #pragma unroll
    for (int o = 16; o > 0; o >>= 1) ss += __shfl_xor_sync(0xffffffff, ss, o);
    float inv = 1.f / fmaxf(sqrtf(ss), 1e-12f);
    #pragma unroll
    for (int r = 0; r < 4; r++)
        out[(size_t)n*128 + lane + 32*r] = v[r] * inv;
}

extern "C" void kernel_launch(void* const* d_in, const int* in_sizes, int n_in,
                              void* d_out, int out_size) {
    const float* pcd_xyz = (const float*)d_in[0];
    const float* rgb_xyz = (const float*)d_in[1];
    const float* pcd_f   = (const float*)d_in[2];
    const float* rgb_f   = (const float*)d_in[3];
    const float* cc1_w = (const float*)d_in[4];  const float* cc1_b = (const float*)d_in[5];
    const float* cc_bn = (const float*)d_in[6];
    const float* cc2_w = (const float*)d_in[7];  const float* cc2_b = (const float*)d_in[8];
    const float* co1_w = (const float*)d_in[9];  const float* co1_b = (const float*)d_in[10];
    const float* co_bn = (const float*)d_in[11];
    const float* co2_w = (const float*)d_in[12]; const float* co2_b = (const float*)d_in[13];
    const float* dh1_w = (const float*)d_in[14]; const float* dh1_b = (const float*)d_in[15];
    const float* dh1_bn= (const float*)d_in[16];
    const float* dh2_w = (const float*)d_in[17]; const float* dh2_b = (const float*)d_in[18];
    const float* dh2_bn= (const float*)d_in[19];
    const float* dh3_w = (const float*)d_in[20]; const float* dh3_b = (const float*)d_in[21];
    const float* sh1_w = (const float*)d_in[22]; const float* sh1_b = (const float*)d_in[23];
    const float* sh_bn = (const float*)d_in[24];
    const float* sh2_w = (const float*)d_in[25]; const float* sh2_b = (const float*)d_in[26];
    float* out = (float*)d_out;

    float *bufA, *bufB, *bufC, *bns, *bnt;
    cudaGetSymbolAddress((void**)&bufA, d_bufA);
    cudaGetSymbolAddress((void**)&bufB, d_bufB);
    cudaGetSymbolAddress((void**)&bufC, d_bufC);
    cudaGetSymbolAddress((void**)&bns,  d_bns);
    cudaGetSymbolAddress((void**)&bnt,  d_bnt);

    // ---- spatial grid + 3NN + gathers ----
    k_clear<<<(NCELL+255)/256, 256>>>();
    k_build<<<(NR+255)/256, 256>>>(rgb_xyz);
    k_3nn<<<(NP+127)/128, 128>>>(pcd_xyz);
    k_gather<<<(NP*128+255)/256, 256>>>(rgb_f);

    // ---- fold BNs ----
    k_bnprep<<<2, 256>>>(cc_bn, 384, 0);
    k_bnprep<<<1, 256>>>(co_bn, 256, 1);
    k_bnprep<<<1, 256>>>(dh1_bn, 160, 2);
    k_bnprep<<<1, 256>>>(dh2_bn, 160, 3);
    k_bnprep<<<1, 256>>>(sh_bn, 128, 4);

    const int NB = NP/64; // 256 column blocks
    // cc1: bufB(384) = relu(bn(W384x384 @ bufA(384)))
    k_gemm<true ><<<dim3(NB,6), 256>>>(cc1_w, bufA, bufB, cc1_b, bns+0,     bnt+0,     384, 384);
    // cc2: bufC rows 0..127 = W128x384 @ bufB   (rows 128..255 already hold max_features)
    k_gemm<false><<<dim3(NB,2), 256>>>(cc2_w, bufB, bufC, cc2_b, nullptr, nullptr, 128, 384);
    // full rows 0..31 = pcd_features (bufB free after cc2)
    cudaMemcpyAsync(bufB, pcd_f, (size_t)32*NP*sizeof(float), cudaMemcpyDeviceToDevice);
    // co1: bufA(256) = relu(bn(W256x256 @ bufC(256)))
    k_gemm<true ><<<dim3(NB,4), 256>>>(co1_w, bufC, bufA, co1_b, bns+384,   bnt+384,   256, 256);
    // co2: attach -> bufB rows 32..159
    k_gemm<false><<<dim3(NB,2), 256>>>(co2_w, bufA, bufB + (size_t)32*NP, co2_b, nullptr, nullptr, 128, 256);
    // dh1: bufC(160) = relu(bn(W160x160 @ bufB(160)))
    k_gemm<true ><<<dim3(NB,3), 256>>>(dh1_w, bufB, bufC, dh1_b, bns+2*384, bnt+2*384, 160, 160);
    // dh2: bufA(160)
    k_gemm<true ><<<dim3(NB,3), 256>>>(dh2_w, bufC, bufA, dh2_b, bns+3*384, bnt+3*384, 160, 160);
    // dh3: fp = bufB(128)
    k_gemm<false><<<dim3(NB,2), 256>>>(dh3_w, bufA, bufB, dh3_b, nullptr, nullptr, 128, 160);
    // sh1: s = bufC(128)
    k_gemm<true ><<<dim3(NB,2), 256>>>(sh1_w, bufB, bufC, sh1_b, bns+4*384, bnt+4*384, 128, 128);

    // ---- outputs: [pcd_xyz (NP*3)] [scores (NP)] [vf (NP*128)] ----
    cudaMemcpyAsync(out, pcd_xyz, (size_t)NP*3*sizeof(float), cudaMemcpyDeviceToDevice);
    k_score<<<NP/256, 256>>>(sh2_w, sh2_b, out + (size_t)NP*3);
    k_vf<<<(NP*32)/256, 256>>>(out + (size_t)NP*4);
}

// round 3
// speedup vs baseline: 1.8385x; 1.8385x over previous
#include <cuda_runtime.h>
#include <math.h>
#include <stdint.h>

#define NP 16384
#define NR 8192
#define GRIDN 13
#define NCELL (GRIDN*GRIDN*GRIDN)
#define CAP 64
#define RADIUS2 (0.075f*0.075f)

// ---------------- static scratch ----------------
__device__ int    d_cellCnt[NCELL];
__device__ float4 d_cellPts[NCELL*CAP];
__device__ int    d_nbr[NP*3];
__device__ float  d_bufA[384*NP];   // point-major activation buffers
__device__ float  d_bufB[384*NP];
__device__ float  d_bufC[256*NP];
__device__ float  d_bns[5*384];
__device__ float  d_bnt[5*384];

// ---------------- spatial grid build ----------------
__global__ void k_clear() {
    int i = blockIdx.x*blockDim.x + threadIdx.x;
    if (i < NCELL) d_cellCnt[i] = 0;
}
__device__ __forceinline__ int cidx(float v) {
    int c = (int)(v * (float)GRIDN);
    return c < 0 ? 0 : (c > GRIDN-1 ? GRIDN-1 : c);
}
__global__ void k_build(const float* __restrict__ rgb) {
    int i = blockIdx.x*blockDim.x + threadIdx.x;
    if (i >= NR) return;
    float x = rgb[3*i], y = rgb[3*i+1], z = rgb[3*i+2];
    int c = (cidx(x)*GRIDN + cidx(y))*GRIDN + cidx(z);
    int p = atomicAdd(&d_cellCnt[c], 1);
    if (p < CAP) d_cellPts[c*CAP + p] = make_float4(x, y, z, __int_as_float(i));
}
__global__ void k_3nn(const float* __restrict__ pcd) {
    int i = blockIdx.x*blockDim.x + threadIdx.x;
    if (i >= NP) return;
    float x = pcd[3*i], y = pcd[3*i+1], z = pcd[3*i+2];
    int cx = cidx(x), cy = cidx(y), cz = cidx(z);
    int x0 = max(cx-1,0), x1 = min(cx+1,GRIDN-1);
    int y0 = max(cy-1,0), y1 = min(cy+1,GRIDN-1);
    int z0 = max(cz-1,0), z1 = min(cz+1,GRIDN-1);
    float b0 = 3.4e38f, b1 = 3.4e38f, b2 = 3.4e38f;
    int   i0 = NR, i1 = NR, i2 = NR;
    for (int ax = x0; ax <= x1; ax++)
    for (int ay = y0; ay <= y1; ay++)
    for (int az = z0; az <= z1; az++) {
        int c = (ax*GRIDN + ay)*GRIDN + az;
        int cnt = min(d_cellCnt[c], CAP);
        const float4* pts = &d_cellPts[c*CAP];
        for (int p = 0; p < cnt; p++) {
            float4 q = pts[p];
            float dx = x - q.x, dy = y - q.y, dz = z - q.z;
            float d = fmaf(dx, dx, fmaf(dy, dy, dz*dz));
            if (d <= RADIUS2 && d < b2) {
                int qi = __float_as_int(q.w);
                if (d < b0)      { b2=b1;i2=i1; b1=b0;i1=i0; b0=d;i0=qi; }
                else if (d < b1) { b2=b1;i2=i1; b1=d; i1=qi; }
                else             { b2=d; i2=qi; }
            }
        }
    }
    d_nbr[3*i] = i0; d_nbr[3*i+1] = i1; d_nbr[3*i+2] = i2;
}

// ---------------- generic channel-major -> point-major transpose ----------------
__global__ void k_trans(const float* __restrict__ in, float* __restrict__ out,
                        int C, int N, int ostride, int ocoff) {
    __shared__ float t[32][33];
    int nb = blockIdx.x * 32;
    int cb = blockIdx.y * 32;
    int tx = threadIdx.x, ty = threadIdx.y;
    #pragma unroll
    for (int i = 0; i < 32; i += 8) {
        int c = cb + ty + i;
        t[ty+i][tx] = (c < C) ? in[(size_t)c*N + nb + tx] : 0.f;
    }
    __syncthreads();
    #pragma unroll
    for (int i = 0; i < 32; i += 8) {
        int c = cb + tx;
        if (c < C) out[(size_t)(nb + ty + i)*ostride + ocoff + c] = t[tx][ty+i];
    }
}

// ---------------- gather (point-major): x_cat rows + max features ----------------
__global__ void k_gather_pm(const float* __restrict__ rgbt /* [NR][128] */) {
    int t = blockIdx.x*blockDim.x + threadIdx.x;
    int n = t >> 5, lane = t & 31;
    if (n >= NP) return;
    int n0 = d_nbr[3*n], n1 = d_nbr[3*n+1], n2 = d_nbr[3*n+2];
    float4 z = make_float4(0.f,0.f,0.f,0.f);
    float4 v0 = (n0 < NR) ? *(const float4*)&rgbt[(size_t)n0*128 + lane*4] : z;
    float4 v1 = (n1 < NR) ? *(const float4*)&rgbt[(size_t)n1*128 + lane*4] : z;
    float4 v2 = (n2 < NR) ? *(const float4*)&rgbt[(size_t)n2*128 + lane*4] : z;
    size_t rb = (size_t)n*384 + lane*4;
    *(float4*)&d_bufA[rb]       = v0;
    *(float4*)&d_bufA[rb + 128] = v1;
    *(float4*)&d_bufA[rb + 256] = v2;
    float4 m;
    m.x = fmaxf(fmaxf(v0.x,v1.x),v2.x);
    m.y = fmaxf(fmaxf(v0.y,v1.y),v2.y);
    m.z = fmaxf(fmaxf(v0.z,v1.z),v2.z);
    m.w = fmaxf(fmaxf(v0.w,v1.w),v2.w);
    *(float4*)&d_bufC[(size_t)n*256 + 128 + lane*4] = m;
}

// ---------------- fold eval-mode BN into scale/shift ----------------
__global__ void k_bnprep(const float* __restrict__ bn, int C, int slot) {
    int c = blockIdx.x*blockDim.x + threadIdx.x;
    if (c >= C) return;
    float g = bn[c], b = bn[C+c], m = bn[2*C+c], v = bn[3*C+c];
    float s = g * rsqrtf(v + 1e-5f);
    d_bns[slot*384 + c] = s;
    d_bnt[slot*384 + c] = b - m*s;
}

// ---------------- tf32 warp-MMA helpers ----------------
__device__ __forceinline__ uint32_t f2tf(float f) {
    uint32_t u;
    asm("cvt.rna.tf32.f32 %0, %1;" : "=r"(u) : "f"(f));
    return u;
}
__device__ __forceinline__ void mma_tf32(float* c, const uint32_t* a, const uint32_t* b) {
    asm volatile(
        "mma.sync.aligned.m16n8k8.row.col.f32.tf32.tf32.f32 "
        "{%0,%1,%2,%3}, {%4,%5,%6,%7}, {%8,%9}, {%0,%1,%2,%3};"
        : "+f"(c[0]), "+f"(c[1]), "+f"(c[2]), "+f"(c[3])
        : "r"(a[0]), "r"(a[1]), "r"(a[2]), "r"(a[3]), "r"(b[0]), "r"(b[1]));
}

// ---------------- tensor-core GEMM (mma.sync tf32) ----------------
// Y[pt][coloff + m] = act( W[m, :] . X[pt, :] + bias[m] )
// X point-major [NP][K]; W row-major [Mout][K]; Y row stride Cout.
// CTA: 128 pts x 128 ch. 8 warps: 4 (pts) x 2 (ch). Warp: 32 pts x 64 ch.
__global__ void __launch_bounds__(256, 2)
k_mma(const float* __restrict__ X, const float* __restrict__ Wt,
      float* __restrict__ Y, const float* __restrict__ bias,
      const float* __restrict__ bns, const float* __restrict__ bnt,
      int K, int Mout, int Cout, int coloff, int bnrelu)
{
    __shared__ float A_s[128][36];   // pts x k-chunk
    __shared__ float B_s[128][36];   // ch  x k-chunk
    const int tid = threadIdx.x;
    const int wid = tid >> 5, lane = tid & 31;
    const int warp_m = wid & 3, warp_n = wid >> 2;
    const int by = blockIdx.y;
    const int ncols = min(128, Mout - by*128);
    const size_t rowbase = (size_t)blockIdx.x * 128;
    const int l4 = lane >> 2, lm = lane & 3;

    float acc[2][8][4];
    #pragma unroll
    for (int i = 0; i < 2; i++)
        #pragma unroll
        for (int j = 0; j < 8; j++)
            #pragma unroll
            for (int q = 0; q < 4; q++) acc[i][j][q] = 0.f;

    const int NC = K >> 5;
    for (int c = 0; c < NC; c++) {
        int k0 = c << 5;
        // load A: 128 rows x 32 floats (8 float4/row)
        #pragma unroll
        for (int it = 0; it < 4; it++) {
            int idx = tid + it*256;
            int r = idx >> 3, q = idx & 7;
            *(float4*)&A_s[r][q*4] = *(const float4*)&X[(rowbase + r)*(size_t)K + k0 + q*4];
        }
        // load B: ncols rows x 32 floats
        for (int idx = tid; idx < ncols*8; idx += 256) {
            int r = idx >> 3, q = idx & 7;
            *(float4*)&B_s[r][q*4] = *(const float4*)&Wt[(size_t)(by*128 + r)*K + k0 + q*4];
        }
        __syncthreads();

        #pragma unroll
        for (int kk = 0; kk < 32; kk += 8) {
            uint32_t a[2][4];
            #pragma unroll
            for (int mt = 0; mt < 2; mt++) {
                int rb = warp_m*32 + mt*16;
                a[mt][0] = f2tf(A_s[rb + l4     ][kk + lm]);
                a[mt][1] = f2tf(A_s[rb + l4 + 8 ][kk + lm]);
                a[mt][2] = f2tf(A_s[rb + l4     ][kk + lm + 4]);
                a[mt][3] = f2tf(A_s[rb + l4 + 8 ][kk + lm + 4]);
            }
            uint32_t b[8][2];
            #pragma unroll
            for (int nt = 0; nt < 8; nt++) {
                int nb = warp_n*64 + nt*8;
                b[nt][0] = f2tf(B_s[nb + l4][kk + lm]);
                b[nt][1] = f2tf(B_s[nb + l4][kk + lm + 4]);
            }
            #pragma unroll
            for (int mt = 0; mt < 2; mt++)
                #pragma unroll
                for (int nt = 0; nt < 8; nt++)
                    mma_tf32(acc[mt][nt], a[mt], b[nt]);
        }
        __syncthreads();
    }

    // epilogue: bias/BN/ReLU, write point-major
    #pragma unroll
    for (int nt = 0; nt < 8; nt++) {
        int nb = warp_n*64 + nt*8;
        if (nb >= ncols) break;
        int ch = nb + 2*lm;                 // local channel (pair ch, ch+1)
        int m  = by*128 + ch;               // global output channel
        float bi0 = __ldg(&bias[m]),   bi1 = __ldg(&bias[m+1]);
        float s0 = 0.f, s1 = 0.f, t0 = 0.f, t1 = 0.f;
        if (bnrelu) {
            s0 = __ldg(&bns[m]); s1 = __ldg(&bns[m+1]);
            t0 = __ldg(&bnt[m]); t1 = __ldg(&bnt[m+1]);
        }
        #pragma unroll
        for (int mt = 0; mt < 2; mt++) {
            int r0 = warp_m*32 + mt*16 + l4;
            #pragma unroll
            for (int h = 0; h < 2; h++) {   // h=0: rows r0 (c0,c1); h=1: rows r0+8 (c2,c3)
                int pt = (int)rowbase + r0 + h*8;
                float x0 = acc[mt][nt][2*h]   + bi0;
                float x1 = acc[mt][nt][2*h+1] + bi1;
                if (bnrelu) {
                    x0 = fmaxf(fmaf(x0, s0, t0), 0.f);
                    x1 = fmaxf(fmaf(x1, s1, t1), 0.f);
                }
                float2 v = make_float2(x0, x1);
                *(float2*)&Y[(size_t)pt*Cout + coloff + m - by*128 + (size_t)by*128] = v;
                // note: coloff + global m
            }
        }
    }
}

// ---------------- score head (warp per point) ----------------
__global__ void k_score(const float* __restrict__ w, const float* __restrict__ b,
                        const float* __restrict__ S, float* __restrict__ out) {
    int t = blockIdx.x*blockDim.x + threadIdx.x;
    int n = t >> 5, lane = t & 31;
    if (n >= NP) return;
    float4 sv = *(const float4*)&S[(size_t)n*128 + lane*4];
    float4 wv = *(const float4*)&w[lane*4];
    float acc = sv.x*wv.x + sv.y*wv.y + sv.z*wv.z + sv.w*wv.w;
    #pragma unroll
    for (int o = 16; o > 0; o >>= 1) acc += __shfl_xor_sync(0xffffffff, acc, o);
    if (lane == 0) out[n] = 1.f / (1.f + expf(-(acc + b[0])));
}

// ---------------- L2-normalize rows (warp per point) ----------------
__global__ void k_vf(const float* __restrict__ FP, float* __restrict__ out) {
    int t = blockIdx.x*blockDim.x + threadIdx.x;
    int n = t >> 5, lane = t & 31;
    if (n >= NP) return;
    float4 v = *(const float4*)&FP[(size_t)n*128 + lane*4];
    float ss = v.x*v.x + v.y*v.y + v.z*v.z + v.w*v.w;
    #pragma unroll
    for (int o = 16; o > 0; o >>= 1) ss += __shfl_xor_sync(0xffffffff, ss, o);
    float inv = 1.f / fmaxf(sqrtf(ss), 1e-12f);
    v.x *= inv; v.y *= inv; v.z *= inv; v.w *= inv;
    *(float4*)&out[(size_t)n*128 + lane*4] = v;
}

extern "C" void kernel_launch(void* const* d_in, const int* in_sizes, int n_in,
                              void* d_out, int out_size) {
    const float* pcd_xyz = (const float*)d_in[0];
    const float* rgb_xyz = (const float*)d_in[1];
    const float* pcd_f   = (const float*)d_in[2];
    const float* rgb_f   = (const float*)d_in[3];
    const float* cc1_w = (const float*)d_in[4];  const float* cc1_b = (const float*)d_in[5];
    const float* cc_bn = (const float*)d_in[6];
    const float* cc2_w = (const float*)d_in[7];  const float* cc2_b = (const float*)d_in[8];
    const float* co1_w = (const float*)d_in[9];  const float* co1_b = (const float*)d_in[10];
    const float* co_bn = (const float*)d_in[11];
    const float* co2_w = (const float*)d_in[12]; const float* co2_b = (const float*)d_in[13];
    const float* dh1_w = (const float*)d_in[14]; const float* dh1_b = (const float*)d_in[15];
    const float* dh1_bn= (const float*)d_in[16];
    const float* dh2_w = (const float*)d_in[17]; const float* dh2_b = (const float*)d_in[18];
    const float* dh2_bn= (const float*)d_in[19];
    const float* dh3_w = (const float*)d_in[20]; const float* dh3_b = (const float*)d_in[21];
    const float* sh1_w = (const float*)d_in[22]; const float* sh1_b = (const float*)d_in[23];
    const float* sh_bn = (const float*)d_in[24];
    const float* sh2_w = (const float*)d_in[25]; const float* sh2_b = (const float*)d_in[26];
    float* out = (float*)d_out;

    float *bufA, *bufB, *bufC, *bns, *bnt;
    cudaGetSymbolAddress((void**)&bufA, d_bufA);
    cudaGetSymbolAddress((void**)&bufB, d_bufB);
    cudaGetSymbolAddress((void**)&bufC, d_bufC);
    cudaGetSymbolAddress((void**)&bns,  d_bns);
    cudaGetSymbolAddress((void**)&bnt,  d_bnt);

    // ---- spatial grid + 3NN ----
    k_clear<<<(NCELL+255)/256, 256>>>();
    k_build<<<(NR+255)/256, 256>>>(rgb_xyz);
    k_3nn<<<(NP+127)/128, 128>>>(pcd_xyz);

    // ---- transpose rgb features to point-major (into bufB scratch) + gather ----
    k_trans<<<dim3(NR/32, 4), dim3(32,8)>>>(rgb_f, bufB, 128, NR, 128, 0);
    k_gather_pm<<<(NP*32)/256, 256>>>(bufB);

    // ---- fold BNs ----
    k_bnprep<<<2, 256>>>(cc_bn, 384, 0);
    k_bnprep<<<1, 256>>>(co_bn, 256, 1);
    k_bnprep<<<1, 256>>>(dh1_bn, 160, 2);
    k_bnprep<<<1, 256>>>(dh2_bn, 160, 3);
    k_bnprep<<<1, 256>>>(sh_bn, 128, 4);

    // ---- tf32 mma.sync GEMM chain (point-major activations) ----
    // cc1: bufA[NP][384] -> bufB[NP][384], BN+ReLU
    k_mma<<<dim3(128,3), 256>>>(bufA, cc1_w, bufB, cc1_b, bns,       bnt,       384, 384, 384, 0, 1);
    // cc2: bufB[384] -> bufC[NP][256] cols 0..127 (cols 128..255 = max features)
    k_mma<<<dim3(128,1), 256>>>(bufB, cc2_w, bufC, cc2_b, nullptr,   nullptr,   384, 128, 256, 0, 0);
    // co1: bufC[256] -> bufA[NP][256], BN+ReLU
    k_mma<<<dim3(128,2), 256>>>(bufC, co1_w, bufA, co1_b, bns+384,   bnt+384,   256, 256, 256, 0, 1);
    // pcd_features -> bufB[NP][160] cols 0..31
    k_trans<<<dim3(NP/32, 1), dim3(32,8)>>>(pcd_f, bufB, 32, NP, 160, 0);
    // co2: bufA[256] -> bufB[NP][160] cols 32..159
    k_mma<<<dim3(128,1), 256>>>(bufA, co2_w, bufB, co2_b, nullptr,   nullptr,   256, 128, 160, 32, 0);
    // dh1: bufB[160] -> bufC[NP][160], BN+ReLU
    k_mma<<<dim3(128,2), 256>>>(bufB, dh1_w, bufC, dh1_b, bns+2*384, bnt+2*384, 160, 160, 160, 0, 1);
    // dh2: bufC[160] -> bufA[NP][160], BN+ReLU
    k_mma<<<dim3(128,2), 256>>>(bufC, dh2_w, bufA, dh2_b, bns+3*384, bnt+3*384, 160, 160, 160, 0, 1);
    // dh3: bufA[160] -> bufB[NP][128]  (fp)
    k_mma<<<dim3(128,1), 256>>>(bufA, dh3_w, bufB, dh3_b, nullptr,   nullptr,   160, 128, 128, 0, 0);
    // sh1: bufB[128] -> bufC[NP][128], BN+ReLU
    k_mma<<<dim3(128,1), 256>>>(bufB, sh1_w, bufC, sh1_b, bns+4*384, bnt+4*384, 128, 128, 128, 0, 1);

    // ---- outputs: [pcd_xyz NP*3][scores NP][vf NP*128] ----
    cudaMemcpyAsync(out, pcd_xyz, (size_t)NP*3*sizeof(float), cudaMemcpyDeviceToDevice);
    k_score<<<(NP*32)/256, 256>>>(sh2_w, sh2_b, bufC, out + (size_t)NP*3);
    k_vf<<<(NP*32)/256, 256>>>(bufB, out + (size_t)NP*4);
}

// round 5
// speedup vs baseline: 4.2531x; 2.3134x over previous
#include <cuda_runtime.h>
#include <cuda_fp16.h>
#include <math.h>
#include <stdint.h>

#define NP 16384
#define NR 8192
#define GRIDN 13
#define NCELL (GRIDN*GRIDN*GRIDN)
#define CAP 64
#define RADIUS2 (0.075f*0.075f)

// ---------------- static scratch ----------------
__device__ int    d_cellCnt[NCELL];
__device__ float4 d_cellPts[NCELL*CAP];
__device__ int    d_nbr[NP*3];
__device__ unsigned short d_hA[384*NP];
__device__ unsigned short d_hB[384*NP];
__device__ unsigned short d_hC[256*NP];
__device__ unsigned short d_hw[382976];
__device__ float  d_bns[5*384];
__device__ float  d_bnt[5*384];

// ---------------- PTX helpers ----------------
__device__ __forceinline__ uint32_t smem_u32(const void* p) {
    uint32_t a;
    asm("{ .reg .u64 t; cvta.to.shared.u64 t, %1; cvt.u32.u64 %0, t; }" : "=r"(a) : "l"(p));
    return a;
}
__device__ __forceinline__ void cpasync16(uint32_t s, const void* g, int sz) {
    asm volatile("cp.async.cg.shared.global [%0], [%1], 16, %2;" :: "r"(s), "l"(g), "r"(sz));
}
#define CP_COMMIT() asm volatile("cp.async.commit_group;")
#define CP_WAIT0()  asm volatile("cp.async.wait_group 0;")
#define CP_WAIT1()  asm volatile("cp.async.wait_group 1;")
#define LDSM4(r0,r1,r2,r3,a) \
    asm volatile("ldmatrix.sync.aligned.m8n8.x4.shared.b16 {%0,%1,%2,%3},[%4];" \
        : "=r"(r0),"=r"(r1),"=r"(r2),"=r"(r3) : "r"(a))
#define LDSM4T(r0,r1,r2,r3,a) \
    asm volatile("ldmatrix.sync.aligned.m8n8.x4.trans.shared.b16 {%0,%1,%2,%3},[%4];" \
        : "=r"(r0),"=r"(r1),"=r"(r2),"=r"(r3) : "r"(a))
__device__ __forceinline__ void mma16(float* c, const uint32_t* a, uint32_t b0, uint32_t b1) {
    asm volatile(
        "mma.sync.aligned.m16n8k16.row.col.f32.f16.f16.f32 "
        "{%0,%1,%2,%3},{%4,%5,%6,%7},{%8,%9},{%0,%1,%2,%3};"
        : "+f"(c[0]), "+f"(c[1]), "+f"(c[2]), "+f"(c[3])
        : "r"(a[0]), "r"(a[1]), "r"(a[2]), "r"(a[3]), "r"(b0), "r"(b1));
}

// ---------------- spatial grid build ----------------
__global__ void k_clear() {
    int i = blockIdx.x*blockDim.x + threadIdx.x;
    if (i < NCELL) d_cellCnt[i] = 0;
}
__device__ __forceinline__ int cidx(float v) {
    int c = (int)(v * (float)GRIDN);
    return c < 0 ? 0 : (c > GRIDN-1 ? GRIDN-1 : c);
}
__global__ void k_build(const float* __restrict__ rgb) {
    int i = blockIdx.x*blockDim.x + threadIdx.x;
    if (i >= NR) return;
    float x = rgb[3*i], y = rgb[3*i+1], z = rgb[3*i+2];
    int c = (cidx(x)*GRIDN + cidx(y))*GRIDN + cidx(z);
    int p = atomicAdd(&d_cellCnt[c], 1);
    if (p < CAP) d_cellPts[c*CAP + p] = make_float4(x, y, z, __int_as_float(i));
}
__global__ void k_3nn(const float* __restrict__ pcd) {
    int i = blockIdx.x*blockDim.x + threadIdx.x;
    if (i >= NP) return;
    float x = pcd[3*i], y = pcd[3*i+1], z = pcd[3*i+2];
    int cx = cidx(x), cy = cidx(y), cz = cidx(z);
    int x0 = max(cx-1,0), x1 = min(cx+1,GRIDN-1);
    int y0 = max(cy-1,0), y1 = min(cy+1,GRIDN-1);
    int z0 = max(cz-1,0), z1 = min(cz+1,GRIDN-1);
    float b0 = 3.4e38f, b1 = 3.4e38f, b2 = 3.4e38f;
    int   i0 = NR, i1 = NR, i2 = NR;
    for (int ax = x0; ax <= x1; ax++)
    for (int ay = y0; ay <= y1; ay++)
    for (int az = z0; az <= z1; az++) {
        int c = (ax*GRIDN + ay)*GRIDN + az;
        int cnt = min(d_cellCnt[c], CAP);
        const float4* pts = &d_cellPts[c*CAP];
        for (int p = 0; p < cnt; p++) {
            float4 q = pts[p];
            float dx = x - q.x, dy = y - q.y, dz = z - q.z;
            float d = fmaf(dx, dx, fmaf(dy, dy, dz*dz));
            if (d <= RADIUS2 && d < b2) {
                int qi = __float_as_int(q.w);
                if (d < b0)      { b2=b1;i2=i1; b1=b0;i1=i0; b0=d;i0=qi; }
                else if (d < b1) { b2=b1;i2=i1; b1=d; i1=qi; }
                else             { b2=d; i2=qi; }
            }
        }
    }
    d_nbr[3*i] = i0; d_nbr[3*i+1] = i1; d_nbr[3*i+2] = i2;
}

// ---------------- ch-major fp32 -> point-major fp16 transpose ----------------
__global__ void k_trans16(const float* __restrict__ in, __half* __restrict__ out,
                          int C, int N, int ostride, int ocoff) {
    __shared__ float t[32][33];
    int nb = blockIdx.x * 32;
    int cb = blockIdx.y * 32;
    int tx = threadIdx.x, ty = threadIdx.y;
    #pragma unroll
    for (int i = 0; i < 32; i += 8) {
        int c = cb + ty + i;
        t[ty+i][tx] = (c < C) ? in[(size_t)c*N + nb + tx] : 0.f;
    }
    __syncthreads();
    #pragma unroll
    for (int i = 0; i < 32; i += 8) {
        int c = cb + tx;
        if (c < C) out[(size_t)(nb + ty + i)*ostride + ocoff + c] = __float2half(t[tx][ty+i]);
    }
}

// ---------------- gather (fp16): x_cat + max features ----------------
__global__ void k_gather16(const unsigned short* __restrict__ rgbt /* [NR][128] */) {
    int t = blockIdx.x*blockDim.x + threadIdx.x;
    int n = t >> 5, lane = t & 31;
    if (n >= NP) return;
    int n0 = d_nbr[3*n], n1 = d_nbr[3*n+1], n2 = d_nbr[3*n+2];
    uint2 z = make_uint2(0u, 0u);
    uint2 u0 = (n0 < NR) ? *(const uint2*)&rgbt[(size_t)n0*128 + lane*4] : z;
    uint2 u1 = (n1 < NR) ? *(const uint2*)&rgbt[(size_t)n1*128 + lane*4] : z;
    uint2 u2 = (n2 < NR) ? *(const uint2*)&rgbt[(size_t)n2*128 + lane*4] : z;
    size_t rb = (size_t)n*384 + lane*4;
    *(uint2*)&d_hA[rb]       = u0;
    *(uint2*)&d_hA[rb + 128] = u1;
    *(uint2*)&d_hA[rb + 256] = u2;
    __half2 a0 = *(__half2*)&u0.x, a1 = *(__half2*)&u0.y;
    __half2 b0 = *(__half2*)&u1.x, b1 = *(__half2*)&u1.y;
    __half2 c0 = *(__half2*)&u2.x, c1 = *(__half2*)&u2.y;
    __half2 m0 = __hmax2(__hmax2(a0, b0), c0);
    __half2 m1 = __hmax2(__hmax2(a1, b1), c1);
    uint2 mu; mu.x = *(uint32_t*)&m0; mu.y = *(uint32_t*)&m1;
    *(uint2*)&d_hC[(size_t)n*256 + 128 + lane*4] = mu;
}

// ---------------- fold BN (all 5 in one launch) ----------------
__global__ void k_bnprep5(const float* b0, const float* b1, const float* b2,
                          const float* b3, const float* b4) {
    const int Cs[5] = {384, 256, 160, 160, 128};
    const float* ps[5] = {b0, b1, b2, b3, b4};
    int slot = blockIdx.x;
    const float* bn = ps[slot];
    int C = Cs[slot];
    for (int c = threadIdx.x; c < C; c += blockDim.x) {
        float g = bn[c], b = bn[C+c], m = bn[2*C+c], v = bn[3*C+c];
        float s = g * rsqrtf(v + 1e-5f);
        d_bns[slot*384 + c] = s;
        d_bnt[slot*384 + c] = b - m*s;
    }
}

// ---------------- weight convert fp32[M][K] -> fp16[K][M] (9 segments) ----------------
struct WSegs { const float* s[8]; int M[8]; int K[8]; int off[8]; };
__global__ void k_wcvt(WSegs ws) {
    int t = blockIdx.x*blockDim.x + threadIdx.x;
    #pragma unroll
    for (int i = 0; i < 8; i++) {
        int sz = ws.M[i] * ws.K[i];
        if (t < sz) {
            int m = t / ws.K[i], k = t % ws.K[i];
            d_hw[ws.off[i] + (size_t)k * ws.M[i] + m] = __half_as_ushort(__float2half(ws.s[i][t]));
            return;
        }
        t -= sz;
    }
}

// ---------------- fp16 tensor-core GEMM (mma.sync m16n8k16) ----------------
// Y[pt][coloff+m] = act( W[m,:] . X[pt,:] + bias[m] ).
// X fp16 point-major [NP][K]; W16 fp16 k-major [K][Mout]; Y fp16, row stride Cout.
// CTA 128 pts x 128 ch, 8 warps (4 pts x 2 ch), warp 32x64. BK=64, double-buffered cp.async.
#define ASTR 72
#define BSTR 136
#define A_BYTES (128*ASTR*2)
#define STAGE   (A_BYTES + 64*BSTR*2)
__global__ void __launch_bounds__(256, 2)
k_mma(const __half* __restrict__ X, const __half* __restrict__ W16,
      __half* __restrict__ Y, const float* __restrict__ bias,
      const float* __restrict__ bns, const float* __restrict__ bnt,
      int K, int Mout, int Cout, int coloff, int bnrelu)
{
    extern __shared__ __align__(16) unsigned char smem[];
    uint32_t sbase = smem_u32(smem);
    const int tid = threadIdx.x;
    const int wid = tid >> 5, lane = tid & 31;
    const int warp_m = wid & 3, warp_n = wid >> 2;
    const int by = blockIdx.y;
    const size_t rowbase = (size_t)blockIdx.x * 128;
    const int NC = (K + 63) >> 6;

    float acc[2][8][4];
    #pragma unroll
    for (int i = 0; i < 2; i++)
        #pragma unroll
        for (int j = 0; j < 8; j++)
            #pragma unroll
            for (int q = 0; q < 4; q++) acc[i][j][q] = 0.f;

    // chunk issue: A 1024 x 16B + B 1024 x 16B via cp.async
    auto issue = [&](int c, int s) {
        int k0 = c << 6;
        uint32_t As = sbase + s*STAGE;
        uint32_t Bs = As + A_BYTES;
        #pragma unroll
        for (int i = 0; i < 4; i++) {
            int idx = tid + i*256;
            int r = idx >> 3, q = idx & 7;
            int kg = k0 + q*8;
            int sz = (kg < K) ? 16 : 0;
            const __half* g = X + (rowbase + r)*(size_t)K + min(kg, K-8);
            cpasync16(As + (r*ASTR + q*8)*2, g, sz);
        }
        #pragma unroll
        for (int i = 0; i < 4; i++) {
            int idx = tid + i*256;
            int kr = idx >> 4, qn = idx & 15;
            int kg = k0 + kr;
            int ng = by*128 + qn*8;
            int sz = (kg < K && ng < Mout) ? 16 : 0;
            const __half* g = W16 + (size_t)min(kg, K-1)*Mout + min(ng, Mout-8);
            cpasync16(Bs + (kr*BSTR + qn*8)*2, g, sz);
        }
        CP_COMMIT();
    };

    issue(0, 0);
    const int li = lane & 15;
    const int h8 = (lane >> 4) << 3;

    for (int c = 0; c < NC; c++) {
        if (c + 1 < NC) { issue(c+1, (c+1)&1); CP_WAIT1(); }
        else            { CP_WAIT0(); }
        __syncthreads();
        uint32_t As = sbase + (c&1)*STAGE;
        uint32_t Bs = As + A_BYTES;
        #pragma unroll
        for (int kk = 0; kk < 64; kk += 16) {
            uint32_t a[2][4];
            #pragma unroll
            for (int mt = 0; mt < 2; mt++) {
                uint32_t ad = As + (((warp_m*32 + mt*16 + li)*ASTR) + kk + h8)*2;
                LDSM4(a[mt][0], a[mt][1], a[mt][2], a[mt][3], ad);
            }
            uint32_t b[4][4];
            #pragma unroll
            for (int nt2 = 0; nt2 < 4; nt2++) {
                uint32_t bd = Bs + ((kk + li)*BSTR + warp_n*64 + nt2*16 + h8)*2;
                LDSM4T(b[nt2][0], b[nt2][1], b[nt2][2], b[nt2][3], bd);
            }
            #pragma unroll
            for (int mt = 0; mt < 2; mt++)
                #pragma unroll
                for (int nt = 0; nt < 8; nt++)
                    mma16(acc[mt][nt], a[mt], b[nt>>1][(nt&1)*2], b[nt>>1][(nt&1)*2+1]);
        }
        __syncthreads();
    }

    // epilogue: bias/BN/ReLU -> fp16
    const int g = lane >> 2, tp = (lane & 3) * 2;
    #pragma unroll
    for (int nt = 0; nt < 8; nt++) {
        int base = by*128 + warp_n*64 + nt*8;
        if (base >= Mout) break;
        int m = base + tp;
        float bi0 = __ldg(&bias[m]), bi1 = __ldg(&bias[m+1]);
        float s0 = 0.f, s1 = 0.f, t0 = 0.f, t1 = 0.f;
        if (bnrelu) {
            s0 = __ldg(&bns[m]); s1 = __ldg(&bns[m+1]);
            t0 = __ldg(&bnt[m]); t1 = __ldg(&bnt[m+1]);
        }
        #pragma unroll
        for (int mt = 0; mt < 2; mt++) {
            int pt0 = (int)rowbase + warp_m*32 + mt*16 + g;
            #pragma unroll
            for (int h = 0; h < 2; h++) {
                int pt = pt0 + h*8;
                float x0 = acc[mt][nt][2*h]   + bi0;
                float x1 = acc[mt][nt][2*h+1] + bi1;
                if (bnrelu) {
                    x0 = fmaxf(fmaf(x0, s0, t0), 0.f);
                    x1 = fmaxf(fmaf(x1, s1, t1), 0.f);
                }
                *(__half2*)&Y[(size_t)pt*Cout + coloff + m] = __floats2half2_rn(x0, x1);
            }
        }
    }
}

// ---------------- score head (warp per point) ----------------
__global__ void k_score(const float* __restrict__ w, const float* __restrict__ b,
                        const unsigned short* __restrict__ S, float* __restrict__ out) {
    int t = blockIdx.x*blockDim.x + threadIdx.x;
    int n = t >> 5, lane = t & 31;
    if (n >= NP) return;
    uint2 su = *(const uint2*)&S[(size_t)n*128 + lane*4];
    __half2 s0 = *(__half2*)&su.x, s1 = *(__half2*)&su.y;
    float4 wv = *(const float4*)&w[lane*4];
    float acc = __low2float(s0)*wv.x + __high2float(s0)*wv.y
              + __low2float(s1)*wv.z + __high2float(s1)*wv.w;
    #pragma unroll
    for (int o = 16; o > 0; o >>= 1) acc += __shfl_xor_sync(0xffffffff, acc, o);
    if (lane == 0) out[n] = 1.f / (1.f + expf(-(acc + b[0])));
}

// ---------------- L2-normalize rows (warp per point) ----------------
__global__ void k_vf(const unsigned short* __restrict__ FP, float* __restrict__ out) {
    int t = blockIdx.x*blockDim.x + threadIdx.x;
    int n = t >> 5, lane = t & 31;
    if (n >= NP) return;
    uint2 su = *(const uint2*)&FP[(size_t)n*128 + lane*4];
    __half2 s0 = *(__half2*)&su.x, s1 = *(__half2*)&su.y;
    float v0 = __low2float(s0), v1 = __high2float(s0);
    float v2 = __low2float(s1), v3 = __high2float(s1);
    float ss = v0*v0 + v1*v1 + v2*v2 + v3*v3;
    #pragma unroll
    for (int o = 16; o > 0; o >>= 1) ss += __shfl_xor_sync(0xffffffff, ss, o);
    float inv = 1.f / fmaxf(sqrtf(ss), 1e-12f);
    float4 r = make_float4(v0*inv, v1*inv, v2*inv, v3*inv);
    *(float4*)&out[(size_t)n*128 + lane*4] = r;
}

extern "C" void kernel_launch(void* const* d_in, const int* in_sizes, int n_in,
                              void* d_out, int out_size) {
    const float* pcd_xyz = (const float*)d_in[0];
    const float* rgb_xyz = (const float*)d_in[1];
    const float* pcd_f   = (const float*)d_in[2];
    const float* rgb_f   = (const float*)d_in[3];
    const float* cc1_w = (const float*)d_in[4];  const float* cc1_b = (const float*)d_in[5];
    const float* cc_bn = (const float*)d_in[6];
    const float* cc2_w = (const float*)d_in[7];  const float* cc2_b = (const float*)d_in[8];
    const float* co1_w = (const float*)d_in[9];  const float* co1_b = (const float*)d_in[10];
    const float* co_bn = (const float*)d_in[11];
    const float* co2_w = (const float*)d_in[12]; const float* co2_b = (const float*)d_in[13];
    const float* dh1_w = (const float*)d_in[14]; const float* dh1_b = (const float*)d_in[15];
    const float* dh1_bn= (const float*)d_in[16];
    const float* dh2_w = (const float*)d_in[17]; const float* dh2_b = (const float*)d_in[18];
    const float* dh2_bn= (const float*)d_in[19];
    const float* dh3_w = (const float*)d_in[20]; const float* dh3_b = (const float*)d_in[21];
    const float* sh1_w = (const float*)d_in[22]; const float* sh1_b = (const float*)d_in[23];
    const float* sh_bn = (const float*)d_in[24];
    const float* sh2_w = (const float*)d_in[25]; const float* sh2_b = (const float*)d_in[26];
    float* out = (float*)d_out;

    unsigned short *hA, *hB, *hC, *hw;
    float *bns, *bnt;
    cudaGetSymbolAddress((void**)&hA, d_hA);
    cudaGetSymbolAddress((void**)&hB, d_hB);
    cudaGetSymbolAddress((void**)&hC, d_hC);
    cudaGetSymbolAddress((void**)&hw, d_hw);
    cudaGetSymbolAddress((void**)&bns, d_bns);
    cudaGetSymbolAddress((void**)&bnt, d_bnt);

    cudaFuncSetAttribute(k_mma, cudaFuncAttributeMaxDynamicSharedMemorySize, 2*STAGE);

    // weight segment table: fp32 [M][K] -> fp16 [K][M] at offset
    WSegs ws;
    const float* srcs[8] = {cc1_w, cc2_w, co1_w, co2_w, dh1_w, dh2_w, dh3_w, sh1_w};
    int Ms[8]   = {384, 128, 256, 128, 160, 160, 128, 128};
    int Ks[8]   = {384, 384, 256, 256, 160, 160, 160, 128};
    int offs[8] = {0, 147456, 196608, 262144, 294912, 320512, 346112, 366592};
    for (int i = 0; i < 8; i++) { ws.s[i] = srcs[i]; ws.M[i] = Ms[i]; ws.K[i] = Ks[i]; ws.off[i] = offs[i]; }

    // ---- prep: grid/3NN, rgb transpose, gather, BN fold, weight convert ----
    k_clear<<<(NCELL+255)/256, 256>>>();
    k_build<<<(NR+255)/256, 256>>>(rgb_xyz);
    k_3nn<<<(NP+127)/128, 128>>>(pcd_xyz);
    k_trans16<<<dim3(NR/32, 4), dim3(32,8)>>>(rgb_f, (__half*)hB, 128, NR, 128, 0);
    k_gather16<<<(NP*32)/256, 256>>>(hB);
    k_bnprep5<<<5, 384>>>(cc_bn, co_bn, dh1_bn, dh2_bn, sh_bn);
    k_wcvt<<<(382976+255)/256, 256>>>(ws);

    // ---- fp16 mma GEMM chain ----
    const __half *XA = (const __half*)hA, *XB = (const __half*)hB, *XC = (const __half*)hC;
    __half *YA = (__half*)hA, *YB = (__half*)hB, *YC = (__half*)hC;
    const __half* W = (const __half*)hw;
    // cc1: hA[384] -> hB[384], BN+ReLU
    k_mma<<<dim3(128,3), 256, 2*STAGE>>>(XA, W+offs[0], YB, cc1_b, bns,       bnt,       384, 384, 384, 0, 1);
    // cc2: hB[384] -> hC cols 0..127 (stride 256; cols 128..255 = max features)
    k_mma<<<dim3(128,1), 256, 2*STAGE>>>(XB, W+offs[1], YC, cc2_b, nullptr,   nullptr,   384, 128, 256, 0, 0);
    // co1: hC[256] -> hA[256], BN+ReLU
    k_mma<<<dim3(128,2), 256, 2*STAGE>>>(XC, W+offs[2], YA, co1_b, bns+384,   bnt+384,   256, 256, 256, 0, 1);
    // pcd_features -> hB cols 0..31 (stride 160)
    k_trans16<<<dim3(NP/32, 1), dim3(32,8)>>>(pcd_f, (__half*)hB, 32, NP, 160, 0);
    // co2: hA[256] -> hB cols 32..159
    k_mma<<<dim3(128,1), 256, 2*STAGE>>>(XA, W+offs[3], YB, co2_b, nullptr,   nullptr,   256, 128, 160, 32, 0);
    // dh1: hB[160] -> hC[160], BN+ReLU
    k_mma<<<dim3(128,2), 256, 2*STAGE>>>(XB, W+offs[4], YC, dh1_b, bns+2*384, bnt+2*384, 160, 160, 160, 0, 1);
    // dh2: hC[160] -> hA[160], BN+ReLU
    k_mma<<<dim3(128,2), 256, 2*STAGE>>>(XC, W+offs[5], YA, dh2_b, bns+3*384, bnt+3*384, 160, 160, 160, 0, 1);
    // dh3: hA[160] -> hB[128]  (fp)
    k_mma<<<dim3(128,1), 256, 2*STAGE>>>(XA, W+offs[6], YB, dh3_b, nullptr,   nullptr,   160, 128, 128, 0, 0);
    // sh1: hB[128] -> hC[128], BN+ReLU
    k_mma<<<dim3(128,1), 256, 2*STAGE>>>(XB, W+offs[7], YC, sh1_b, bns+4*384, bnt+4*384, 128, 128, 128, 0, 1);

    // ---- outputs: [pcd_xyz NP*3][scores NP][vf NP*128] ----
    cudaMemcpyAsync(out, pcd_xyz, (size_t)NP*3*sizeof(float), cudaMemcpyDeviceToDevice);
    k_score<<<(NP*32)/256, 256>>>(sh2_w, sh2_b, hC, out + (size_t)NP*3);
    k_vf<<<(NP*32)/256, 256>>>(hB, out + (size_t)NP*4);
}